// round 4
// baseline (speedup 1.0000x reference)
#include <cuda_runtime.h>
#include <cstdint>

// CompressK: mean-pool over sliding windows of 32 rows, stride 16.
// k: (BATCH*SEQ_LEN, 4, 128) fp32 -> row = 512 floats
// out: (4092, 4, 128) fp32 followed by cu_comp (BATCH+1) as fp32 values.
//
// Block-sum sharing: chunk c = (S_c + S_{c+1}) / 32 where S_j = sum of
// 16-row block j. A CUDA block computing CH consecutive chunks computes
// CH+1 block-sums -> reads (CH+1)/(2*CH) of the naive 2x traffic.
//
// Scalar-float granularity: 512 threads/block (one float column each) so
// CH=8 (low traffic) still yields 8192 warps total = ~55 warps/SM.

#define BATCH 4
#define SEQ_LEN 16384
#define ROW_FLOATS 512            // 4 heads * 128 dim
#define CHUNKS_PER_BATCH 1023     // (16384-32)/16 + 1
#define TOTAL_CHUNKS (BATCH * CHUNKS_PER_BATCH)   // 4092
#define CH 8                      // chunks per CUDA block
#define BLOCKS_PER_BATCH ((CHUNKS_PER_BATCH + CH - 1) / CH)  // 128
#define OUT_FLOATS ((size_t)TOTAL_CHUNKS * ROW_FLOATS)       // 2,095,104

__global__ __launch_bounds__(ROW_FLOATS) void compress_k_kernel(
    const float* __restrict__ k, float* __restrict__ out)
{
    const int tid = threadIdx.x;                 // 0..511, float column
    const int batch = blockIdx.x / BLOCKS_PER_BATCH;
    const int bi    = blockIdx.x % BLOCKS_PER_BATCH;

    // Fused cu_comp tail (fp32 values; exact for these magnitudes)
    if (blockIdx.x == 0 && tid <= BATCH) {
        out[OUT_FLOATS + tid] = (float)(tid * CHUNKS_PER_BATCH);
    }

    const int c_begin = bi * CH;                 // first local chunk
    int nch = CHUNKS_PER_BATCH - c_begin;
    if (nch > CH) nch = CH;
    if (nch <= 0) return;

    const size_t base_row = (size_t)batch * SEQ_LEN + (size_t)c_begin * 16;
    const float* src = k + base_row * ROW_FLOATS + tid;

    const float inv32 = 1.0f / 32.0f;

    float sPrev = 0.0f;

    // block-sums j = 0..nch ; chunk (c_begin + j - 1) = (S_{j-1} + S_j)/32
    for (int j = 0; j <= nch; ++j) {
        const float* p = src + (size_t)j * 16 * ROW_FLOATS;

        // 4 independent accumulator chains; all 16 LDG.32 issue up front.
        float a0 = 0.f, a1 = 0.f, a2 = 0.f, a3 = 0.f;
        #pragma unroll
        for (int r = 0; r < 4; ++r) {
            float v0 = p[(size_t)(4 * r + 0) * ROW_FLOATS];
            float v1 = p[(size_t)(4 * r + 1) * ROW_FLOATS];
            float v2 = p[(size_t)(4 * r + 2) * ROW_FLOATS];
            float v3 = p[(size_t)(4 * r + 3) * ROW_FLOATS];
            a0 += v0; a1 += v1; a2 += v2; a3 += v3;
        }
        float s = (a0 + a1) + (a2 + a3);

        if (j > 0) {
            const size_t oc = (size_t)batch * CHUNKS_PER_BATCH + c_begin + (j - 1);
            out[oc * ROW_FLOATS + tid] = (sPrev + s) * inv32;
        }
        sPrev = s;
    }
}

extern "C" void kernel_launch(void* const* d_in, const int* in_sizes, int n_in,
                              void* d_out, int out_size)
{
    const float* k = (const float*)d_in[0];

    dim3 grid(BATCH * BLOCKS_PER_BATCH);
    compress_k_kernel<<<grid, ROW_FLOATS>>>(k, (float*)d_out);
}

// round 5
// speedup vs baseline: 1.1617x; 1.1617x over previous
#include <cuda_runtime.h>
#include <cstdint>

// CompressK: mean-pool over sliding windows of 32 rows, stride 16.
// k: (BATCH*SEQ_LEN, 4, 128) fp32 -> row = 512 floats = 128 float4
// out: (4092, 4, 128) fp32 followed by cu_comp (BATCH+1) as fp32 values.
//
// Block-sum sharing: chunk c = (S_c + S_{c+1}) / 32, S_j = sum of 16-row
// block j. CH=8 chunks/block -> 9 block-sums -> 9/16 of naive read traffic.
//
// Row-split: 512 threads = 4 quarter-groups x 128 float4 columns. Each
// thread sums 4 rows (float4) per block-sum; partials combined via a
// double-buffered smem stage (one __syncthreads per block-sum).

#define BATCH 4
#define SEQ_LEN 16384
#define ROW_FLOATS 512
#define ROW_F4 128
#define CHUNKS_PER_BATCH 1023     // (16384-32)/16 + 1
#define TOTAL_CHUNKS (BATCH * CHUNKS_PER_BATCH)   // 4092
#define CH 8
#define BLOCKS_PER_BATCH ((CHUNKS_PER_BATCH + CH - 1) / CH)  // 128
#define OUT_FLOATS ((size_t)TOTAL_CHUNKS * ROW_FLOATS)       // 2,095,104
#define NTHREADS 512

__global__ __launch_bounds__(NTHREADS) void compress_k_kernel(
    const float4* __restrict__ k4, float* __restrict__ out)
{
    __shared__ float4 part[2][4][ROW_F4];   // [buf][quarter][float4 col]

    const int tid  = threadIdx.x;           // 0..511
    const int col4 = tid & 127;             // float4 column
    const int q    = tid >> 7;              // row quarter 0..3

    const int batch = blockIdx.x / BLOCKS_PER_BATCH;
    const int bi    = blockIdx.x % BLOCKS_PER_BATCH;

    // Fused cu_comp tail (fp32 values; exact for these magnitudes)
    if (blockIdx.x == 0 && tid <= BATCH) {
        out[OUT_FLOATS + tid] = (float)(tid * CHUNKS_PER_BATCH);
    }

    const int c_begin = bi * CH;
    int nch = CHUNKS_PER_BATCH - c_begin;
    if (nch > CH) nch = CH;

    const size_t base_row = (size_t)batch * SEQ_LEN + (size_t)c_begin * 16;
    // this thread's first row within each 16-row block-sum: q*4
    const float4* src = k4 + (base_row + (size_t)q * 4) * ROW_F4 + col4;

    // scalar-column view for the combine/output phase
    const float* partf = (const float*)part;   // [buf*4 + q][512 floats]

    const float inv32 = 1.0f / 32.0f;
    float sPrev = 0.0f;
    int buf = 0;

    const size_t out_base = ((size_t)batch * CHUNKS_PER_BATCH + c_begin) * ROW_FLOATS + tid;

    for (int j = 0; j <= nch; ++j) {
        // 4 independent LDG.128
        const float4* p = src + (size_t)j * 16 * ROW_F4;
        float4 v0 = p[0 * ROW_F4];
        float4 v1 = p[1 * ROW_F4];
        float4 v2 = p[2 * ROW_F4];
        float4 v3 = p[3 * ROW_F4];
        float4 ps;
        ps.x = (v0.x + v1.x) + (v2.x + v3.x);
        ps.y = (v0.y + v1.y) + (v2.y + v3.y);
        ps.z = (v0.z + v1.z) + (v2.z + v3.z);
        ps.w = (v0.w + v1.w) + (v2.w + v3.w);
        part[buf][q][col4] = ps;

        __syncthreads();

        // combine: thread owns scalar float column tid
        const float* pb = partf + (size_t)buf * 4 * ROW_FLOATS;
        float s = (pb[0 * ROW_FLOATS + tid] + pb[1 * ROW_FLOATS + tid])
                + (pb[2 * ROW_FLOATS + tid] + pb[3 * ROW_FLOATS + tid]);

        if (j > 0) {
            out[out_base + (size_t)(j - 1) * ROW_FLOATS] = (sPrev + s) * inv32;
        }
        sPrev = s;
        buf ^= 1;
    }
}

extern "C" void kernel_launch(void* const* d_in, const int* in_sizes, int n_in,
                              void* d_out, int out_size)
{
    const float4* k4 = (const float4*)d_in[0];

    dim3 grid(BATCH * BLOCKS_PER_BATCH);   // 512
    compress_k_kernel<<<grid, NTHREADS>>>(k4, (float*)d_out);
}